// round 10
// baseline (speedup 1.0000x reference)
#include <cuda_runtime.h>
#include <cuda_bf16.h>
#include <cstdint>

// RaySampler: N=32 cameras, resolution=512 (M=262144 rays/cam).
// Output layout (fp32): [ray_origins (N,M,3)] then [ray_dirs (N,M,3)].
// Write-bandwidth bound: 201.3 MB of stores, ~3 KB of broadcast reads.
//
// Each thread handles 4 consecutive rays in one image row:
//   m0 = 4*t, row = m0>>9, col = m0&511.
// 4 rays * 3 floats = 12 floats = 3 float4 stores per output tensor,
// all 16B aligned because (n*M + m0)*3 is a multiple of 4.

static constexpr int RES = 512;
static constexpr int M_RAYS = RES * RES;          // 262144
static constexpr float INV_RES = 1.0f / (float)RES;

__global__ void __launch_bounds__(256)
ray_sampler_kernel(const float* __restrict__ cam,     // (N,4,4)
                   const float* __restrict__ intr,    // (N,3,3)
                   float4* __restrict__ out_org,      // (N,M,3) as float4[N*M*3/4]
                   float4* __restrict__ out_dir)      // (N,M,3) as float4[N*M*3/4]
{
    const int n  = blockIdx.y;
    const int t  = blockIdx.x * blockDim.x + threadIdx.x;  // 0 .. M/4-1
    const int m0 = t << 2;
    const int row = m0 >> 9;        // resolution = 512
    const int col = m0 & (RES - 1);

    // Camera params (tiny, L1-broadcast).
    const float* Mn = cam + n * 16;
    const float a0 = Mn[0],  b0 = Mn[1],  c0 = -Mn[2];
    const float a1 = Mn[4],  b1 = Mn[5],  c1 = -Mn[6];
    const float a2 = Mn[8],  b2 = Mn[9],  c2 = -Mn[10];
    const float ox = Mn[3],  oy = Mn[7],  oz = Mn[11];

    const float* In = intr + n * 9;
    const float fx = In[0], sk = In[1], cx = In[2];
    const float fy = In[4], cy = In[5];
    const float inv_fx = 1.0f / fx;
    const float inv_fy = 1.0f / fy;

    // y_cam constant across the 4 rays (same image row).
    const float y_cam  = ((float)row + 0.5f) * INV_RES;
    const float y_lift = -(y_cam - cy) * inv_fy;
    // x_lift = (x_cam - cx + (cy - y_cam)*sk/fy) / fx
    const float xbase  = -cx + (cy - y_cam) * sk * inv_fy;

    float dx[4], dy[4], dz[4];
#pragma unroll
    for (int k = 0; k < 4; ++k) {
        const float x_cam  = ((float)(col + k) + 0.5f) * INV_RES;
        const float x_lift = (x_cam + xbase) * inv_fx;
        const float wx = fmaf(a0, x_lift, fmaf(b0, y_lift, c0));
        const float wy = fmaf(a1, x_lift, fmaf(b1, y_lift, c1));
        const float wz = fmaf(a2, x_lift, fmaf(b2, y_lift, c2));
        const float nrm = fmaxf(sqrtf(fmaf(wx, wx, fmaf(wy, wy, wz * wz))), 1e-12f);
        const float inv = 1.0f / nrm;
        dx[k] = wx * inv;
        dy[k] = wy * inv;
        dz[k] = wz * inv;
    }

    // float4 index: ((n*M + m0)*3) / 4  — exact since m0 is a multiple of 4.
    const size_t bi = ((size_t)n * M_RAYS + (size_t)m0) * 3u / 4u;

    out_dir[bi + 0] = make_float4(dx[0], dy[0], dz[0], dx[1]);
    out_dir[bi + 1] = make_float4(dy[1], dz[1], dx[2], dy[2]);
    out_dir[bi + 2] = make_float4(dz[2], dx[3], dy[3], dz[3]);

    out_org[bi + 0] = make_float4(ox, oy, oz, ox);
    out_org[bi + 1] = make_float4(oy, oz, ox, oy);
    out_org[bi + 2] = make_float4(oz, ox, oy, oz);
}

extern "C" void kernel_launch(void* const* d_in, const int* in_sizes, int n_in,
                              void* d_out, int out_size)
{
    const float* cam  = (const float*)d_in[0];   // (N,4,4) fp32
    const float* intr = (const float*)d_in[1];   // (N,3,3) fp32
    const int N = in_sizes[0] / 16;              // 32

    float4* out_org = (float4*)d_out;
    float4* out_dir = (float4*)d_out + ((size_t)N * M_RAYS * 3u) / 4u;

    // M/4 rays-groups per camera, 256 threads per block.
    dim3 block(256);
    dim3 grid(M_RAYS / (4 * 256), N);            // (256, 32)
    ray_sampler_kernel<<<grid, block>>>(cam, intr, out_org, out_dir);
}

// round 11
// speedup vs baseline: 1.2766x; 1.2766x over previous
#include <cuda_runtime.h>
#include <cuda_bf16.h>
#include <cstdint>

// RaySampler: N=32 cameras, resolution=512 (M=262144 rays/cam).
// Output (fp32): [ray_origins (N,M,3)][ray_dirs (N,M,3)] = 201.3 MB of writes.
//
// R10 was L1-sector-bound (74% L1, 37% DRAM): 3x sector amplification from
// 48B-strided float4 stores. This version assigns ONE output float4 per
// thread (perfectly coalesced stores) and recomputes the 2 rays that float4
// touches (compute is nearly free: fma pipe was at 11%).
//
//   g = global float4 index into the dirs tensor, q = g/3, p = g%3
//   quad q = rays 4q..4q+3 of camera n = q>>16; the float4 is the window
//   [4p, 4p+4) of the quad's 12 floats -> needs rays (4q+p) and (4q+p+1).

static constexpr int RES = 512;
static constexpr int M_RAYS = RES * RES;                  // 262144
static constexpr int QUADS_PER_CAM = M_RAYS / 4;          // 65536
static constexpr float INV_RES = 1.0f / (float)RES;

__device__ __forceinline__ float3 ray_dir(
    int col, float xbase, float inv_fx, float y_lift,
    float a0, float b0, float c0,
    float a1, float b1, float c1,
    float a2, float b2, float c2)
{
    const float x_cam  = ((float)col + 0.5f) * INV_RES;
    const float x_lift = (x_cam + xbase) * inv_fx;
    const float wx = fmaf(a0, x_lift, fmaf(b0, y_lift, c0));
    const float wy = fmaf(a1, x_lift, fmaf(b1, y_lift, c1));
    const float wz = fmaf(a2, x_lift, fmaf(b2, y_lift, c2));
    float n2 = fmaf(wx, wx, fmaf(wy, wy, wz * wz));
    n2 = fmaxf(n2, 1e-24f);
    const float inv = rsqrtf(n2);
    return make_float3(wx * inv, wy * inv, wz * inv);
}

__global__ void __launch_bounds__(256)
ray_sampler_kernel(const float* __restrict__ cam,     // (N,4,4)
                   const float* __restrict__ intr,    // (N,3,3)
                   float4* __restrict__ out_org,      // N*M*3/4 float4s
                   float4* __restrict__ out_dir)      // N*M*3/4 float4s
{
    const int g = blockIdx.x * blockDim.x + threadIdx.x;   // float4 slot
    const int q = g / 3;                                   // ray quad
    const int p = g - q * 3;                               // window phase

    const int n  = q >> 16;                                // q / QUADS_PER_CAM
    const int mq = q & (QUADS_PER_CAM - 1);
    const int m0 = mq << 2;                                // first ray of quad
    const int row = m0 >> 9;
    const int colA = (m0 & (RES - 1)) + p;                 // ray A = m0+p

    // Camera params (tiny, L1-broadcast; n is warp-uniform except at seams).
    const float* Mn = cam + n * 16;
    const float a0 = Mn[0],  b0 = Mn[1],  c0 = -Mn[2],  ox = Mn[3];
    const float a1 = Mn[4],  b1 = Mn[5],  c1 = -Mn[6],  oy = Mn[7];
    const float a2 = Mn[8],  b2 = Mn[9],  c2 = -Mn[10], oz = Mn[11];

    const float* In = intr + n * 9;
    const float fx = In[0], sk = In[1], cx = In[2];
    const float fy = In[4], cy = In[5];
    const float inv_fx = 1.0f / fx;
    const float inv_fy = 1.0f / fy;

    const float y_cam  = ((float)row + 0.5f) * INV_RES;
    const float y_lift = -(y_cam - cy) * inv_fy;
    const float xbase  = -cx + (cy - y_cam) * sk * inv_fy;

    const float3 A = ray_dir(colA,     xbase, inv_fx, y_lift,
                             a0,b0,c0, a1,b1,c1, a2,b2,c2);
    const float3 B = ray_dir(colA + 1, xbase, inv_fx, y_lift,
                             a0,b0,c0, a1,b1,c1, a2,b2,c2);

    float4 dv, ov;
    if (p == 0) {
        dv = make_float4(A.x, A.y, A.z, B.x);
        ov = make_float4(ox,  oy,  oz,  ox);
    } else if (p == 1) {
        dv = make_float4(A.y, A.z, B.x, B.y);
        ov = make_float4(oy,  oz,  ox,  oy);
    } else {
        dv = make_float4(A.z, B.x, B.y, B.z);
        ov = make_float4(oz,  ox,  oy,  oz);
    }

    out_dir[g] = dv;     // fully coalesced: warp writes 512B contiguous
    out_org[g] = ov;
}

extern "C" void kernel_launch(void* const* d_in, const int* in_sizes, int n_in,
                              void* d_out, int out_size)
{
    const float* cam  = (const float*)d_in[0];   // (N,4,4) fp32
    const float* intr = (const float*)d_in[1];   // (N,3,3) fp32
    const int N = in_sizes[0] / 16;              // 32

    const size_t T4 = (size_t)N * M_RAYS * 3u / 4u;   // 6,291,456 float4s
    float4* out_org = (float4*)d_out;
    float4* out_dir = (float4*)d_out + T4;

    dim3 block(256);
    dim3 grid((unsigned)(T4 / 256));             // 24576 blocks, exact
    ray_sampler_kernel<<<grid, block>>>(cam, intr, out_org, out_dir);
}

// round 12
// speedup vs baseline: 1.5000x; 1.1750x over previous
#include <cuda_runtime.h>
#include <cuda_bf16.h>
#include <cstdint>

// RaySampler: N=32 cameras, resolution=512 (M=262144 rays/cam).
// Output (fp32): [ray_origins (N,M,3)][ray_dirs (N,M,3)] = 201.3 MB of writes.
//
// R11 was issue/compute-limited (issue=68%, alu=31%, DRAM only 50%).
// This version hoists ALL per-camera algebra into a 32-thread precompute
// kernel: unnormalized dir is affine in pixel coords,
//     w(col,row) = P*col + Q*row + R          (P,Q,R per-camera 3-vectors)
// so the hot kernel is: 3 broadcast loads, ~12 FMA, 2 rsqrt, 2 coalesced
// STG.128 (streaming). One output float4 slot per thread (as in R11).

static constexpr int RES = 512;
static constexpr int M_RAYS = RES * RES;                  // 262144
static constexpr int QUADS_PER_CAM = M_RAYS / 4;          // 65536
static constexpr float INV_RES = 1.0f / (float)RES;
static constexpr int MAXN = 1024;

// Per-camera table: [3n+0]=(Px,Py,Pz,ox) [3n+1]=(Qx,Qy,Qz,oy) [3n+2]=(Rx,Ry,Rz,oz)
__device__ float4 g_camtab[MAXN * 3];

__global__ void precompute_kernel(const float* __restrict__ cam,
                                  const float* __restrict__ intr, int N)
{
    const int n = blockIdx.x * blockDim.x + threadIdx.x;
    if (n >= N) return;

    const float* Mn = cam + n * 16;
    const float3 A = make_float3(Mn[0], Mn[4], Mn[8]);    // rot col 0
    const float3 B = make_float3(Mn[1], Mn[5], Mn[9]);    // rot col 1
    const float3 C = make_float3(-Mn[2], -Mn[6], -Mn[10]);// -rot col 2
    const float ox = Mn[3], oy = Mn[7], oz = Mn[11];

    const float* In = intr + n * 9;
    const float fx = In[0], sk = In[1], cx = In[2];
    const float fy = In[4], cy = In[5];
    const float ifx = 1.0f / fx;
    const float ify = 1.0f / fy;

    // x_lift = x_cam*ifx + (cy*sk*ify - cx)*ifx - y_cam*(sk*ify*ifx)
    // y_lift = -y_cam*ify + cy*ify
    // w = A*x_lift + B*y_lift + C
    const float s  = sk * ify * ifx;
    const float rx = (cy * sk * ify - cx) * ifx;
    const float ry = cy * ify;

    float3 P, Q, R;
    P.x = A.x * ifx;                 P.y = A.y * ifx;                 P.z = A.z * ifx;
    Q.x = -(A.x * s + B.x * ify);    Q.y = -(A.y * s + B.y * ify);    Q.z = -(A.z * s + B.z * ify);
    R.x = A.x * rx + B.x * ry + C.x; R.y = A.y * rx + B.y * ry + C.y; R.z = A.z * rx + B.z * ry + C.z;

    // Fold pixel-coordinate scaling: x_cam=(col+0.5)/RES, y_cam=(row+0.5)/RES
    // => w = (P/RES)*col + (Q/RES)*row + (R + 0.5*(P+Q)/RES)
    float3 Pp = make_float3(P.x * INV_RES, P.y * INV_RES, P.z * INV_RES);
    float3 Qp = make_float3(Q.x * INV_RES, Q.y * INV_RES, Q.z * INV_RES);
    float3 Rp = make_float3(R.x + 0.5f * (Pp.x + Qp.x),
                            R.y + 0.5f * (Pp.y + Qp.y),
                            R.z + 0.5f * (Pp.z + Qp.z));

    g_camtab[3 * n + 0] = make_float4(Pp.x, Pp.y, Pp.z, ox);
    g_camtab[3 * n + 1] = make_float4(Qp.x, Qp.y, Qp.z, oy);
    g_camtab[3 * n + 2] = make_float4(Rp.x, Rp.y, Rp.z, oz);
}

__global__ void __launch_bounds__(256)
ray_sampler_kernel(float4* __restrict__ out_org,
                   float4* __restrict__ out_dir)
{
    const unsigned g = blockIdx.x * blockDim.x + threadIdx.x;  // float4 slot
    const unsigned q = g / 3u;                                 // ray quad
    const int p = (int)(g - q * 3u);                           // window phase

    const int n  = (int)(q >> 16);                             // quad/65536
    const int m0 = (int)(q & (QUADS_PER_CAM - 1)) << 2;        // first ray
    const float rowf = (float)(m0 >> 9);
    const float colf = (float)((m0 & (RES - 1)) + p);          // ray A col

    const float4 Pv = g_camtab[3 * n + 0];
    const float4 Qv = g_camtab[3 * n + 1];
    const float4 Rv = g_camtab[3 * n + 2];

    // base = Q*row + R  (shared by both rays)
    const float bx = fmaf(Qv.x, rowf, Rv.x);
    const float by = fmaf(Qv.y, rowf, Rv.y);
    const float bz = fmaf(Qv.z, rowf, Rv.z);

    // ray A (col), ray B (col+1) = A + P
    float ax = fmaf(Pv.x, colf, bx);
    float ay = fmaf(Pv.y, colf, by);
    float az = fmaf(Pv.z, colf, bz);
    float ex = ax + Pv.x;
    float ey = ay + Pv.y;
    float ez = az + Pv.z;

    const float ia = rsqrtf(fmaxf(fmaf(ax, ax, fmaf(ay, ay, az * az)), 1e-24f));
    const float ib = rsqrtf(fmaxf(fmaf(ex, ex, fmaf(ey, ey, ez * ez)), 1e-24f));
    ax *= ia; ay *= ia; az *= ia;
    ex *= ib; ey *= ib; ez *= ib;

    float4 dv, ov;
    if (p == 0) {
        dv = make_float4(ax, ay, az, ex);
        ov = make_float4(Pv.w, Qv.w, Rv.w, Pv.w);
    } else if (p == 1) {
        dv = make_float4(ay, az, ex, ey);
        ov = make_float4(Qv.w, Rv.w, Pv.w, Qv.w);
    } else {
        dv = make_float4(az, ex, ey, ez);
        ov = make_float4(Rv.w, Pv.w, Qv.w, Rv.w);
    }

    __stcs(&out_dir[g], dv);    // streaming: write-once, evict-first
    __stcs(&out_org[g], ov);
}

extern "C" void kernel_launch(void* const* d_in, const int* in_sizes, int n_in,
                              void* d_out, int out_size)
{
    const float* cam  = (const float*)d_in[0];   // (N,4,4) fp32
    const float* intr = (const float*)d_in[1];   // (N,3,3) fp32
    const int N = in_sizes[0] / 16;              // 32

    precompute_kernel<<<(N + 31) / 32, 32>>>(cam, intr, N);

    const size_t T4 = (size_t)N * M_RAYS * 3u / 4u;   // 6,291,456 float4s
    float4* out_org = (float4*)d_out;
    float4* out_dir = (float4*)d_out + T4;

    dim3 block(256);
    dim3 grid((unsigned)(T4 / 256));             // 24576 blocks, exact
    ray_sampler_kernel<<<grid, block>>>(out_org, out_dir);
}